// round 15
// baseline (speedup 1.0000x reference)
#include <cuda_runtime.h>
#include <cuda_fp16.h>
#include <math.h>
#include <stdint.h>

#define NB 32
#define NT 512
#define NC 256
#define ND 1024
#define NH 16
#define NL 6
#define NFF 4096
#define NO 256
#define NQ 8
#define NK 1024
#define NTOK (NB*NT)

#define QKV_SZ  (ND*3*ND)
#define PROJ_SZ (ND*ND)
#define FF1_SZ  (ND*NFF)
#define FF2_SZ  (NFF*ND)
#define OFF_WIN 0
#define OFF_QKV (NC*ND)
#define OFF_PROJ (OFF_QKV + 6*QKV_SZ)
#define OFF_FF1  (OFF_PROJ + 6*PROJ_SZ)
#define OFF_FF2  (OFF_FF1 + 6*FF1_SZ)
#define W_TOTAL  (OFF_FF2 + 6*FF2_SZ)

__device__ float g_last[NB * ND];
__device__ float g_z1  [NB * ND];
__device__ float g_z   [NB * NO];

__device__ __align__(16) __half g_h   [(size_t)NTOK * ND];   // fp16 residual
__device__ __align__(16) __half g_wf  [W_TOTAL];             // weights fp16 [K,N]
__device__ __align__(16) __half g_af  [(size_t)NTOK * ND];
__device__ __align__(16) __half g_ff  [(size_t)NTOK * NFF];
__device__ __align__(16) __half g_xf  [(size_t)NTOK * NC];
__device__ __align__(16) __half g_qkvh[(size_t)NTOK * 3 * ND];

__device__ __forceinline__ float gelu_exact(float v) {
    return 0.5f * v * (1.0f + erff(v * 0.70710678118654752f));
}
__device__ __forceinline__ uint32_t smem_u32(const void* p) {
    uint32_t a;
    asm("{ .reg .u64 t; cvta.to.shared.u64 t, %1; cvt.u32.u64 %0, t; }"
        : "=r"(a) : "l"(p));
    return a;
}
__device__ __forceinline__ void cp16(uint32_t dst, const void* src) {
    asm volatile("cp.async.cg.shared.global [%0], [%1], 16;"
                 :: "r"(dst), "l"(src) : "memory");
}
#define CP_COMMIT() asm volatile("cp.async.commit_group;" ::: "memory")
#define CP_WAIT2()  asm volatile("cp.async.wait_group 2;" ::: "memory")

__device__ __forceinline__ void ldsm_x4(uint32_t* r, uint32_t addr) {
    asm volatile("ldmatrix.sync.aligned.m8n8.x4.shared.b16 {%0,%1,%2,%3}, [%4];"
                 : "=r"(r[0]), "=r"(r[1]), "=r"(r[2]), "=r"(r[3]) : "r"(addr));
}
__device__ __forceinline__ void ldsm_x4_t(uint32_t* r, uint32_t addr) {
    asm volatile("ldmatrix.sync.aligned.m8n8.x4.trans.shared.b16 {%0,%1,%2,%3}, [%4];"
                 : "=r"(r[0]), "=r"(r[1]), "=r"(r[2]), "=r"(r[3]) : "r"(addr));
}
__device__ __forceinline__ void mma_f16(float* d, const uint32_t* a, const uint32_t* b) {
    asm volatile("mma.sync.aligned.m16n8k16.row.col.f32.f16.f16.f32 "
                 "{%0,%1,%2,%3}, {%4,%5,%6,%7}, {%8,%9}, {%0,%1,%2,%3};"
                 : "+f"(d[0]), "+f"(d[1]), "+f"(d[2]), "+f"(d[3])
                 : "r"(a[0]), "r"(a[1]), "r"(a[2]), "r"(a[3]),
                   "r"(b[0]), "r"(b[1]));
}

// ---------------------------------------------------------------------------
// fp16 GEMM. C[M,N] = A[M,K] @ W[K,N]. A fp16 [M,K]; W fp16 [K,N] (natural).
// B fragments via ldmatrix.trans on [K,N] smem tile.
// Block 128x128, BK=32, 256 thr (8 warps 2Mx4N), 3-stage cp.async,
// 2 CTAs/SM to hide barrier bubbles in the tensor pipe.
// MODE 1: +bias +pos(fp32) -> fp16   MODE 2: gelu(+bias) -> fp16
// MODE 3: +bias +extraH(fp16) -> fp16   MODE 4: +bias -> fp16
// ---------------------------------------------------------------------------
#define AT_B   10240              // A tile: 128 rows * 80B
#define BT_OFF 10240
#define BT_B   8704               // B tile: 32 rows * 272B
#define STG_B  (AT_B + BT_B)      // 18944
#define GSMEM  (3*STG_B)          // 56832

__device__ __forceinline__ void load_stage(
    uint32_t sb, int c, int tid, int rowBase, int colBase, int K, int N,
    const __half* __restrict__ A, const __half* __restrict__ B)
{
    size_t koff = (size_t)c * 32;
#pragma unroll
    for (int i = 0; i < 2; i++) {               // A: 128 rows x 64B
        int lin = tid + (i << 8);
        int r = lin >> 2, q = lin & 3;
        cp16(sb + (uint32_t)(r * 80 + q * 16),
             A + (size_t)(rowBase + r) * K + koff + q * 8);
    }
#pragma unroll
    for (int i = 0; i < 2; i++) {               // B: 32 k-rows x 256B
        int lin = tid + (i << 8);
        int r = lin >> 4, q = lin & 15;
        cp16(sb + BT_OFF + (uint32_t)(r * 272 + q * 16),
             B + (koff + r) * (size_t)N + colBase + q * 8);
    }
    CP_COMMIT();
}

template<int MODE>
__global__ __launch_bounds__(256, 2)
void gemm_mma(const __half* __restrict__ A, const __half* __restrict__ B,
              const float* __restrict__ bias, const float* __restrict__ extra,
              const __half* __restrict__ extraH, __half* __restrict__ Ch,
              int M, int N, int K)
{
    extern __shared__ __align__(1024) unsigned char dynsmem[];
    uint32_t sbase = smem_u32(dynsmem);
    const int tid = threadIdx.x;
    const int lane = tid & 31;
    const int warp = tid >> 5;
    const int warpM = warp & 1;
    const int warpN = warp >> 1;
    const int rowBase = blockIdx.y * 128;
    const int colBase = blockIdx.x * 128;
    const int nc = K >> 5;

    float acc[4][4][4];
#pragma unroll
    for (int mt = 0; mt < 4; mt++)
#pragma unroll
        for (int nt = 0; nt < 4; nt++)
#pragma unroll
            for (int e = 0; e < 4; e++) acc[mt][nt][e] = 0.f;

    load_stage(sbase,             0, tid, rowBase, colBase, K, N, A, B);
    load_stage(sbase +   STG_B,   1, tid, rowBase, colBase, K, N, A, B);
    load_stage(sbase + 2*STG_B,   2, tid, rowBase, colBase, K, N, A, B);

    const int aRow = warpM * 64 + (lane & 15);
    const uint32_t aColOff = (uint32_t)((lane >> 4) * 16);
    const int bRowOff = ((lane >> 3) & 1) * 8 + (lane & 7);
    const uint32_t bColB = (uint32_t)(warpN * 64 + ((lane >> 4) & 1) * 16);

    int stage = 0;
    for (int c = 0; c < nc; c++) {
        CP_WAIT2();
        __syncthreads();
        uint32_t sb = sbase + (uint32_t)stage * STG_B;

#pragma unroll
        for (int kk = 0; kk < 2; kk++) {
            uint32_t ah[4][4];
#pragma unroll
            for (int mt = 0; mt < 4; mt++)
                ldsm_x4(ah[mt], sb + (uint32_t)((aRow + mt * 16) * 80)
                              + (uint32_t)(kk * 32) + aColOff);
#pragma unroll
            for (int ng = 0; ng < 2; ng++) {
                uint32_t r[4];
                uint32_t baddr = sb + BT_OFF
                    + (uint32_t)((kk * 16 + bRowOff) * 272)
                    + bColB + (uint32_t)(ng * 32);
                ldsm_x4_t(r, baddr);
#pragma unroll
                for (int mt = 0; mt < 4; mt++) {
                    mma_f16(acc[mt][2 * ng],     ah[mt], r);
                    mma_f16(acc[mt][2 * ng + 1], ah[mt], r + 2);
                }
            }
        }
        __syncthreads();
        if (c + 3 < nc)
            load_stage(sbase + (uint32_t)stage * STG_B, c + 3, tid,
                       rowBase, colBase, K, N, A, B);
        else
            CP_COMMIT();   // empty group keeps wait_group bookkeeping uniform
        stage = (stage == 2) ? 0 : stage + 1;
    }

#pragma unroll
    for (int mt = 0; mt < 4; mt++) {
        int row0 = rowBase + warpM * 64 + mt * 16 + (lane >> 2);
#pragma unroll
        for (int nt = 0; nt < 4; nt++) {
            int col = colBase + warpN * 32 + nt * 8 + (lane & 3) * 2;
            float b0 = bias[col], b1 = bias[col + 1];
#pragma unroll
            for (int half = 0; half < 2; half++) {
                int row = row0 + half * 8;
                float v0 = acc[mt][nt][half * 2 + 0] + b0;
                float v1 = acc[mt][nt][half * 2 + 1] + b1;
                if (MODE == 1) {
                    size_t pr = (size_t)(row & (NT - 1)) * N + col;
                    v0 += extra[pr]; v1 += extra[pr + 1];
                }
                if (MODE == 3) {
                    __half2 e = *(const __half2*)(extraH + (size_t)row * N + col);
                    v0 += __half2float(e.x); v1 += __half2float(e.y);
                }
                if (MODE == 2) { v0 = gelu_exact(v0); v1 = gelu_exact(v1); }
                *(__half2*)(Ch + (size_t)row * N + col) =
                    __half2(__float2half(v0), __float2half(v1));
            }
        }
    }
}

// ---------------- vectorized fp32 -> fp16 convert ----------------
__global__ __launch_bounds__(256)
void cvt4(const float* __restrict__ x, __half* __restrict__ o, size_t n) {
    size_t i = ((size_t)blockIdx.x * 256 + threadIdx.x) * 4;
    if (i < n) {
        float4 v = *(const float4*)(x + i);
        __half2 h0 = __floats2half2_rn(v.x, v.y);
        __half2 h1 = __floats2half2_rn(v.z, v.w);
        uint2 u; u.x = *(uint32_t*)&h0; u.y = *(uint32_t*)&h1;
        *(uint2*)(o + i) = u;
    }
}

// ---------------- LayerNorm over fp16 input: OUT=0 fp32, OUT=1 fp16 --------
template<int OUT>
__global__ __launch_bounds__(256)
void ln_kernel(const __half* __restrict__ x, const float* __restrict__ g,
               const float* __restrict__ b, float* __restrict__ yf,
               __half* __restrict__ yh, size_t rowStride)
{
    __shared__ float red[18];
    const int row = blockIdx.x, tid = threadIdx.x;
    const __half* xr = x + (size_t)row * rowStride;
    uint2 raw = ((const uint2*)xr)[tid];
    float2 p0 = __half22float2(*(__half2*)&raw.x);
    float2 p1 = __half22float2(*(__half2*)&raw.y);
    float v0 = p0.x, v1 = p0.y, v2 = p1.x, v3 = p1.y;
    float s  = v0 + v1 + v2 + v3;
    float sq = v0*v0 + v1*v1 + v2*v2 + v3*v3;
#pragma unroll
    for (int o = 16; o > 0; o >>= 1) {
        s  += __shfl_xor_sync(0xffffffffu, s,  o);
        sq += __shfl_xor_sync(0xffffffffu, sq, o);
    }
    if ((tid & 31) == 0) { red[tid >> 5] = s; red[8 + (tid >> 5)] = sq; }
    __syncthreads();
    if (tid < 32) {
        float ws = (tid < 8) ? red[tid]     : 0.f;
        float wq = (tid < 8) ? red[8 + tid] : 0.f;
#pragma unroll
        for (int o = 4; o > 0; o >>= 1) {
            ws += __shfl_xor_sync(0xffffffffu, ws, o);
            wq += __shfl_xor_sync(0xffffffffu, wq, o);
        }
        if (tid == 0) { red[16] = ws; red[17] = wq; }
    }
    __syncthreads();
    float mean = red[16] * (1.f / ND);
    float var  = red[17] * (1.f / ND) - mean * mean;
    float rstd = rsqrtf(var + 1e-5f);
    float4 gg = ((const float4*)g)[tid];
    float4 bb = ((const float4*)b)[tid];
    float o0 = (v0 - mean) * rstd * gg.x + bb.x;
    float o1 = (v1 - mean) * rstd * gg.y + bb.y;
    float o2 = (v2 - mean) * rstd * gg.z + bb.z;
    float o3 = (v3 - mean) * rstd * gg.w + bb.w;
    if (OUT == 0) {
        float4 o4 = {o0, o1, o2, o3};
        ((float4*)(yf + (size_t)row * ND))[tid] = o4;
    } else {
        size_t base = (size_t)row * ND + tid * 4;
        *(__half2*)(yh + base)     = __half2(__float2half(o0), __float2half(o1));
        *(__half2*)(yh + base + 2) = __half2(__float2half(o2), __float2half(o3));
    }
}

// ---------------------------------------------------------------------------
// Tensor-core flash attention, causal, HD=64 (unchanged).
// ---------------------------------------------------------------------------
#define ASTB 144

__global__ __launch_bounds__(128)
void attn_mma(const __half* __restrict__ qkv, __half* __restrict__ oh)
{
    __shared__ __align__(16) unsigned char sQ[64 * ASTB];
    __shared__ __align__(16) unsigned char sK[64 * ASTB];
    __shared__ __align__(16) unsigned char sV[64 * ASTB];
    const int qt = blockIdx.x, h = blockIdx.y, b = blockIdx.z;
    const int tid = threadIdx.x;
    const int lane = tid & 31, w = tid >> 5;
    uint32_t q_s = smem_u32(sQ), k_s = smem_u32(sK), v_s = smem_u32(sV);

    {
        size_t tok0 = (size_t)(b * NT + qt * 64);
#pragma unroll
        for (int i = 0; i < 4; i++) {
            int idx = tid + i * 128;
            int m = idx >> 3, dq = (idx & 7) * 8;
            *(uint4*)(sQ + m * ASTB + dq * 2) =
                *(const uint4*)(qkv + (tok0 + m) * (3 * ND) + h * 64 + dq);
        }
    }
    __syncthreads();

    uint32_t aQ[4][4];
    {
        uint32_t base = q_s + (uint32_t)((w * 16 + (lane & 15)) * ASTB)
                      + (uint32_t)((lane >> 4) * 16);
#pragma unroll
        for (int kc = 0; kc < 4; kc++) ldsm_x4(aQ[kc], base + kc * 32);
    }

    float oAcc[8][4];
#pragma unroll
    for (int nt = 0; nt < 8; nt++)
#pragma unroll
        for (int e = 0; e < 4; e++) oAcc[nt][e] = 0.f;
    float mA = -1e30f, mB = -1e30f, lA = 0.f, lB = 0.f;
    const int rowA = qt * 64 + w * 16 + (lane >> 2);
    const int rowB = rowA + 8;
    const float scale = 0.125f;

    for (int kt = 0; kt <= qt; kt++) {
        __syncthreads();
        {
            size_t tok0 = (size_t)(b * NT + kt * 64);
#pragma unroll
            for (int i = 0; i < 4; i++) {
                int idx = tid + i * 128;
                int m = idx >> 3, dq = (idx & 7) * 8;
                const __half* src = qkv + (tok0 + m) * (3 * ND) + ND + h * 64 + dq;
                *(uint4*)(sK + m * ASTB + dq * 2) = *(const uint4*)src;
                *(uint4*)(sV + m * ASTB + dq * 2) = *(const uint4*)(src + ND);
            }
        }
        __syncthreads();

        float sAcc[8][4];
#pragma unroll
        for (int nt = 0; nt < 8; nt++)
#pragma unroll
            for (int e = 0; e < 4; e++) sAcc[nt][e] = 0.f;
#pragma unroll
        for (int ng = 0; ng < 4; ng++) {
            uint32_t rbase = k_s
                + (uint32_t)((ng * 16 + ((lane >> 4) & 1) * 8 + (lane & 7)) * ASTB)
                + (uint32_t)(((lane >> 3) & 1) * 16);
#pragma unroll
            for (int kc = 0; kc < 4; kc++) {
                uint32_t r[4];
                ldsm_x4(r, rbase + kc * 32);
                mma_f16(sAcc[2 * ng],     aQ[kc], r);
                mma_f16(sAcc[2 * ng + 1], aQ[kc], r + 2);
            }
        }

        int colBase = kt * 64 + (lane & 3) * 2;
        float tA = -1e30f, tB = -1e30f;
#pragma unroll
        for (int nt = 0; nt < 8; nt++) {
            int c0 = colBase + nt * 8, c1 = c0 + 1;
            sAcc[nt][0] = (c0 <= rowA) ? sAcc[nt][0] * scale : -1e30f;
            sAcc[nt][1] = (c1 <= rowA) ? sAcc[nt][1] * scale : -1e30f;
            sAcc[nt][2] = (c0 <= rowB) ? sAcc[nt][2] * scale : -1e30f;
            sAcc[nt][3] = (c1 <= rowB) ? sAcc[nt][3] * scale : -1e30f;
            tA = fmaxf(tA, fmaxf(sAcc[nt][0], sAcc[nt][1]));
            tB = fmaxf(tB, fmaxf(sAcc[nt][2], sAcc[nt][3]));
        }
        tA = fmaxf(tA, __shfl_xor_sync(0xffffffffu, tA, 1));
        tA = fmaxf(tA, __shfl_xor_sync(0xffffffffu, tA, 2));
        tB = fmaxf(tB, __shfl_xor_sync(0xffffffffu, tB, 1));
        tB = fmaxf(tB, __shfl_xor_sync(0xffffffffu, tB, 2));
        float mnA = fmaxf(mA, tA), mnB = fmaxf(mB, tB);
        float corrA = expf(mA - mnA), corrB = expf(mB - mnB);
        float lsA = 0.f, lsB = 0.f;
#pragma unroll
        for (int nt = 0; nt < 8; nt++) {
            sAcc[nt][0] = expf(sAcc[nt][0] - mnA);
            sAcc[nt][1] = expf(sAcc[nt][1] - mnA);
            sAcc[nt][2] = expf(sAcc[nt][2] - mnB);
            sAcc[nt][3] = expf(sAcc[nt][3] - mnB);
            lsA += sAcc[nt][0] + sAcc[nt][1];
            lsB += sAcc[nt][2] + sAcc[nt][3];
        }
        lsA += __shfl_xor_sync(0xffffffffu, lsA, 1);
        lsA += __shfl_xor_sync(0xffffffffu, lsA, 2);
        lsB += __shfl_xor_sync(0xffffffffu, lsB, 1);
        lsB += __shfl_xor_sync(0xffffffffu, lsB, 2);
        lA = lA * corrA + lsA; mA = mnA;
        lB = lB * corrB + lsB; mB = mnB;
#pragma unroll
        for (int nt = 0; nt < 8; nt++) {
            oAcc[nt][0] *= corrA; oAcc[nt][1] *= corrA;
            oAcc[nt][2] *= corrB; oAcc[nt][3] *= corrB;
        }

        uint32_t aP[4][4];
#pragma unroll
        for (int kc = 0; kc < 4; kc++) {
            __half2 h0 = __floats2half2_rn(sAcc[2*kc][0],   sAcc[2*kc][1]);
            __half2 h1 = __floats2half2_rn(sAcc[2*kc][2],   sAcc[2*kc][3]);
            __half2 h2 = __floats2half2_rn(sAcc[2*kc+1][0], sAcc[2*kc+1][1]);
            __half2 h3 = __floats2half2_rn(sAcc[2*kc+1][2], sAcc[2*kc+1][3]);
            aP[kc][0] = *(uint32_t*)&h0; aP[kc][1] = *(uint32_t*)&h1;
            aP[kc][2] = *(uint32_t*)&h2; aP[kc][3] = *(uint32_t*)&h3;
        }

#pragma unroll
        for (int dg = 0; dg < 4; dg++) {
#pragma unroll
            for (int kc = 0; kc < 4; kc++) {
                uint32_t r[4];
                uint32_t addr = v_s
                    + (uint32_t)((kc * 16 + ((lane >> 3) & 1) * 8 + (lane & 7)) * ASTB)
                    + (uint32_t)(dg * 32) + (uint32_t)(((lane >> 4) & 1) * 16);
                ldsm_x4_t(r, addr);
                mma_f16(oAcc[2 * dg],     aP[kc], r);
                mma_f16(oAcc[2 * dg + 1], aP[kc], r + 2);
            }
        }
    }

    float invA = 1.f / lA, invB = 1.f / lB;
    size_t tokA = (size_t)(b * NT) + rowA;
    size_t tokB = (size_t)(b * NT) + rowB;
    int col0 = h * 64 + (lane & 3) * 2;
#pragma unroll
    for (int nt = 0; nt < 8; nt++) {
        *(__half2*)(oh + tokA * ND + col0 + nt * 8) =
            __half2(__float2half(oAcc[nt][0] * invA), __float2half(oAcc[nt][1] * invA));
        *(__half2*)(oh + tokB * ND + col0 + nt * 8) =
            __half2(__float2half(oAcc[nt][2] * invB), __float2half(oAcc[nt][3] * invB));
    }
}

// ---------------- head + RVQ ----------------
__global__ __launch_bounds__(256)
void small_gemm(const float* __restrict__ A, const float* __restrict__ W,
                const float* __restrict__ bias, float* __restrict__ out,
                int K, int N, int doGelu)
{
    __shared__ float sA[ND];
    const int row = blockIdx.x, tid = threadIdx.x;
    for (int i = tid; i < K; i += 256) sA[i] = A[(size_t)row * K + i];
    __syncthreads();
    for (int col = tid; col < N; col += 256) {
        float acc = 0.f;
        for (int k = 0; k < K; k++) acc += sA[k] * W[(size_t)k * N + col];
        acc += bias[col];
        if (doGelu) acc = gelu_exact(acc);
        out[(size_t)row * N + col] = acc;
    }
}

__global__ __launch_bounds__(256)
void rvq_kernel(const float* __restrict__ z, const float* __restrict__ codebooks,
                const float* __restrict__ layer_scales, float* __restrict__ out)
{
    __shared__ float res[NO];
    __shared__ float bestd[256];
    __shared__ int   besti[256];
    const int row = blockIdx.x, tid = threadIdx.x;
    res[tid] = z[(size_t)row * NO + tid];
    float outv = 0.f;
    for (int q = 0; q < NQ; q++) {
        __syncthreads();
        const float* cb = codebooks + (size_t)q * NK * NO;
        float bd = 1e30f; int bi = 0;
        for (int c = tid; c < NK; c += 256) {
            const float* e = cb + (size_t)c * NO;
            float dot = 0.f, nrm = 0.f;
            for (int d = 0; d < NO; d += 4) {
                float4 e4 = *(const float4*)(e + d);
                dot += res[d]*e4.x + res[d+1]*e4.y + res[d+2]*e4.z + res[d+3]*e4.w;
                nrm += e4.x*e4.x + e4.y*e4.y + e4.z*e4.z + e4.w*e4.w;
            }
            float dist = nrm - 2.f * dot;
            if (dist < bd) { bd = dist; bi = c; }
        }
        bestd[tid] = bd; besti[tid] = bi;
        __syncthreads();
        for (int sft = 128; sft > 0; sft >>= 1) {
            if (tid < sft) {
                float od = bestd[tid + sft]; int oi = besti[tid + sft];
                if (od < bestd[tid] || (od == bestd[tid] && oi < besti[tid])) {
                    bestd[tid] = od; besti[tid] = oi;
                }
            }
            __syncthreads();
        }
        int best = besti[0];
        float sig = 1.f / (1.f + expf(-layer_scales[q]));
        float ev = cb[(size_t)best * NO + tid];
        outv += sig * ev;
        res[tid] = res[tid] - ev;
    }
    out[(size_t)row * NO + tid] = outv;
}

// ---------------------------------------------------------------------------
extern "C" void kernel_launch(void* const* d_in, const int* in_sizes, int n_in,
                              void* d_out, int out_size)
{
    const float* x      = (const float*)d_in[0];
    const float* w_in   = (const float*)d_in[1];
    const float* b_in   = (const float*)d_in[2];
    const float* pos    = (const float*)d_in[3];
    const float* ln1_g  = (const float*)d_in[4];
    const float* ln1_b  = (const float*)d_in[5];
    const float* qkv_w  = (const float*)d_in[6];
    const float* qkv_b  = (const float*)d_in[7];
    const float* proj_w = (const float*)d_in[8];
    const float* proj_b = (const float*)d_in[9];
    const float* ln2_g  = (const float*)d_in[10];
    const float* ln2_b  = (const float*)d_in[11];
    const float* ff1_w  = (const float*)d_in[12];
    const float* ff1_b  = (const float*)d_in[13];
    const float* ff2_w  = (const float*)d_in[14];
    const float* ff2_b  = (const float*)d_in[15];
    const float* lnf_g  = (const float*)d_in[16];
    const float* lnf_b  = (const float*)d_in[17];
    const float* out1_w = (const float*)d_in[18];
    const float* out1_b = (const float*)d_in[19];
    const float* out2_w = (const float*)d_in[20];
    const float* out2_b = (const float*)d_in[21];
    const float* codebooks    = (const float*)d_in[22];
    const float* layer_scales = (const float*)d_in[23];

    float *last, *z1, *z;
    __half *h, *wf, *af, *ff, *xf, *qkvh;
    cudaGetSymbolAddress((void**)&last, g_last);
    cudaGetSymbolAddress((void**)&z1,   g_z1);
    cudaGetSymbolAddress((void**)&z,    g_z);
    cudaGetSymbolAddress((void**)&h,    g_h);
    cudaGetSymbolAddress((void**)&wf,   g_wf);
    cudaGetSymbolAddress((void**)&af,   g_af);
    cudaGetSymbolAddress((void**)&ff,   g_ff);
    cudaGetSymbolAddress((void**)&xf,   g_xf);
    cudaGetSymbolAddress((void**)&qkvh, g_qkvh);

    cudaFuncSetAttribute(gemm_mma<1>, cudaFuncAttributeMaxDynamicSharedMemorySize, GSMEM);
    cudaFuncSetAttribute(gemm_mma<2>, cudaFuncAttributeMaxDynamicSharedMemorySize, GSMEM);
    cudaFuncSetAttribute(gemm_mma<3>, cudaFuncAttributeMaxDynamicSharedMemorySize, GSMEM);
    cudaFuncSetAttribute(gemm_mma<4>, cudaFuncAttributeMaxDynamicSharedMemorySize, GSMEM);

    const dim3 thr(256);
    auto cblk = [](size_t n) { return (unsigned)((n / 4 + 255) / 256); };

    // ---- conversions ----
    cvt4<<<cblk((size_t)NTOK * NC), thr>>>(x, xf, (size_t)NTOK * NC);
    cvt4<<<cblk((size_t)NC * ND), thr>>>(w_in, wf + OFF_WIN, (size_t)NC * ND);
    cvt4<<<cblk((size_t)6 * QKV_SZ), thr>>>(qkv_w,  wf + OFF_QKV,  (size_t)6 * QKV_SZ);
    cvt4<<<cblk((size_t)6 * PROJ_SZ), thr>>>(proj_w, wf + OFF_PROJ, (size_t)6 * PROJ_SZ);
    cvt4<<<cblk((size_t)6 * FF1_SZ), thr>>>(ff1_w,  wf + OFF_FF1,  (size_t)6 * FF1_SZ);
    cvt4<<<cblk((size_t)6 * FF2_SZ), thr>>>(ff2_w,  wf + OFF_FF2,  (size_t)6 * FF2_SZ);

    // ---- h = x @ w_in + b_in + pos (fp16 out) ----
    gemm_mma<1><<<dim3(ND/128, NTOK/128), thr, GSMEM>>>(
        xf, wf + OFF_WIN, b_in, pos, nullptr, h, NTOK, ND, NC);

    for (int l = 0; l < NL; l++) {
        ln_kernel<1><<<NTOK, thr>>>(h, ln1_g + (size_t)l*ND, ln1_b + (size_t)l*ND,
                                    nullptr, af, ND);
        gemm_mma<4><<<dim3(3*ND/128, NTOK/128), thr, GSMEM>>>(
            af, wf + OFF_QKV + (size_t)l*QKV_SZ,
            qkv_b + (size_t)l*3*ND, nullptr, nullptr, qkvh, NTOK, 3*ND, ND);
        attn_mma<<<dim3(NT/64, NH, NB), 128>>>(qkvh, af);
        gemm_mma<3><<<dim3(ND/128, NTOK/128), thr, GSMEM>>>(
            af, wf + OFF_PROJ + (size_t)l*PROJ_SZ,
            proj_b + (size_t)l*ND, nullptr, h, h, NTOK, ND, ND);
        ln_kernel<1><<<NTOK, thr>>>(h, ln2_g + (size_t)l*ND, ln2_b + (size_t)l*ND,
                                    nullptr, af, ND);
        gemm_mma<2><<<dim3(NFF/128, NTOK/128), thr, GSMEM>>>(
            af, wf + OFF_FF1 + (size_t)l*FF1_SZ,
            ff1_b + (size_t)l*NFF, nullptr, nullptr, ff, NTOK, NFF, ND);
        gemm_mma<3><<<dim3(ND/128, NTOK/128), thr, GSMEM>>>(
            ff, wf + OFF_FF2 + (size_t)l*FF2_SZ,
            ff2_b + (size_t)l*ND, nullptr, h, h, NTOK, ND, NFF);
    }

    // ---- head ----
    ln_kernel<0><<<NB, thr>>>(h + (size_t)(NT - 1) * ND, lnf_g, lnf_b,
                              last, nullptr, (size_t)NT * ND);
    small_gemm<<<NB, thr>>>(last, out1_w, out1_b, z1, ND, ND, 1);
    small_gemm<<<NB, thr>>>(z1, out2_w, out2_b, z, ND, NO, 0);
    rvq_kernel<<<NB, thr>>>(z, codebooks, layer_scales, (float*)d_out);
}

// round 16
// speedup vs baseline: 1.4957x; 1.4957x over previous
#include <cuda_runtime.h>
#include <cuda_fp16.h>
#include <math.h>
#include <stdint.h>

#define NB 32
#define NT 512
#define NC 256
#define ND 1024
#define NH 16
#define NL 6
#define NFF 4096
#define NO 256
#define NQ 8
#define NK 1024
#define NTOK (NB*NT)

#define QKV_SZ  (ND*3*ND)
#define PROJ_SZ (ND*ND)
#define FF1_SZ  (ND*NFF)
#define FF2_SZ  (NFF*ND)
#define OFF_WIN 0
#define OFF_QKV (NC*ND)
#define OFF_PROJ (OFF_QKV + 6*QKV_SZ)
#define OFF_FF1  (OFF_PROJ + 6*PROJ_SZ)
#define OFF_FF2  (OFF_FF1 + 6*FF1_SZ)
#define W_TOTAL  (OFF_FF2 + 6*FF2_SZ)

__device__ float g_last[NB * ND];
__device__ float g_z1  [NB * ND];
__device__ float g_z   [NB * NO];

__device__ __align__(16) __half g_h   [(size_t)NTOK * ND];   // fp16 residual
__device__ __align__(16) __half g_wf  [W_TOTAL];             // weights fp16 [K,N]
__device__ __align__(16) __half g_af  [(size_t)NTOK * ND];
__device__ __align__(16) __half g_ff  [(size_t)NTOK * NFF];
__device__ __align__(16) __half g_xf  [(size_t)NTOK * NC];
__device__ __align__(16) __half g_qkvh[(size_t)NTOK * 3 * ND];

__device__ __forceinline__ float gelu_exact(float v) {
    return 0.5f * v * (1.0f + erff(v * 0.70710678118654752f));
}
__device__ __forceinline__ uint32_t smem_u32(const void* p) {
    uint32_t a;
    asm("{ .reg .u64 t; cvta.to.shared.u64 t, %1; cvt.u32.u64 %0, t; }"
        : "=r"(a) : "l"(p));
    return a;
}
__device__ __forceinline__ void cp16(uint32_t dst, const void* src) {
    asm volatile("cp.async.cg.shared.global [%0], [%1], 16;"
                 :: "r"(dst), "l"(src) : "memory");
}
#define CP_COMMIT() asm volatile("cp.async.commit_group;" ::: "memory")
#define CP_WAIT1()  asm volatile("cp.async.wait_group 1;" ::: "memory")
#define CP_WAIT0()  asm volatile("cp.async.wait_group 0;" ::: "memory")

__device__ __forceinline__ void ldsm_x4(uint32_t* r, uint32_t addr) {
    asm volatile("ldmatrix.sync.aligned.m8n8.x4.shared.b16 {%0,%1,%2,%3}, [%4];"
                 : "=r"(r[0]), "=r"(r[1]), "=r"(r[2]), "=r"(r[3]) : "r"(addr));
}
__device__ __forceinline__ void ldsm_x4_t(uint32_t* r, uint32_t addr) {
    asm volatile("ldmatrix.sync.aligned.m8n8.x4.trans.shared.b16 {%0,%1,%2,%3}, [%4];"
                 : "=r"(r[0]), "=r"(r[1]), "=r"(r[2]), "=r"(r[3]) : "r"(addr));
}
__device__ __forceinline__ void mma_f16(float* d, const uint32_t* a, const uint32_t* b) {
    asm volatile("mma.sync.aligned.m16n8k16.row.col.f32.f16.f16.f32 "
                 "{%0,%1,%2,%3}, {%4,%5,%6,%7}, {%8,%9}, {%0,%1,%2,%3};"
                 : "+f"(d[0]), "+f"(d[1]), "+f"(d[2]), "+f"(d[3])
                 : "r"(a[0]), "r"(a[1]), "r"(a[2]), "r"(a[3]),
                   "r"(b[0]), "r"(b[1]));
}

// ---------------------------------------------------------------------------
// fp16 GEMM. C[M,N] = A[M,K] @ W[K,N]. A fp16 [M,K]; W fp16 [K,N] (natural).
// B fragments via ldmatrix.trans on [K,N] smem tile.
// Block 128x128, BK=32, 256 thr (8 warps 2Mx4N), 2-stage cp.async,
// 2 CTAs/SM (launch_bounds) to hide barrier bubbles in the tensor pipe.
// MODE 1: +bias +pos(fp32) -> fp16   MODE 2: gelu(+bias) -> fp16
// MODE 3: +bias +extraH(fp16) -> fp16   MODE 4: +bias -> fp16
// ---------------------------------------------------------------------------
#define AT_B   10240              // A tile: 128 rows * 80B
#define BT_OFF 10240
#define BT_B   8704               // B tile: 32 rows * 272B
#define STG_B  (AT_B + BT_B)      // 18944
#define GSMEM  (2*STG_B)          // 37888

__device__ __forceinline__ void load_stage(
    uint32_t sb, int c, int tid, int rowBase, int colBase, int K, int N,
    const __half* __restrict__ A, const __half* __restrict__ B)
{
    size_t koff = (size_t)c * 32;
#pragma unroll
    for (int i = 0; i < 2; i++) {               // A: 128 rows x 64B
        int lin = tid + (i << 8);
        int r = lin >> 2, q = lin & 3;
        cp16(sb + (uint32_t)(r * 80 + q * 16),
             A + (size_t)(rowBase + r) * K + koff + q * 8);
    }
#pragma unroll
    for (int i = 0; i < 2; i++) {               // B: 32 k-rows x 256B
        int lin = tid + (i << 8);
        int r = lin >> 4, q = lin & 15;
        cp16(sb + BT_OFF + (uint32_t)(r * 272 + q * 16),
             B + (koff + r) * (size_t)N + colBase + q * 8);
    }
    CP_COMMIT();
}

template<int MODE>
__global__ __launch_bounds__(256, 2)
void gemm_mma(const __half* __restrict__ A, const __half* __restrict__ B,
              const float* __restrict__ bias, const float* __restrict__ extra,
              const __half* __restrict__ extraH, __half* __restrict__ Ch,
              int M, int N, int K)
{
    extern __shared__ __align__(1024) unsigned char dynsmem[];
    uint32_t sbase = smem_u32(dynsmem);
    const int tid = threadIdx.x;
    const int lane = tid & 31;
    const int warp = tid >> 5;
    const int warpM = warp & 1;
    const int warpN = warp >> 1;
    const int rowBase = blockIdx.y * 128;
    const int colBase = blockIdx.x * 128;
    const int nc = K >> 5;

    float acc[4][4][4];
#pragma unroll
    for (int mt = 0; mt < 4; mt++)
#pragma unroll
        for (int nt = 0; nt < 4; nt++)
#pragma unroll
            for (int e = 0; e < 4; e++) acc[mt][nt][e] = 0.f;

    load_stage(sbase,         0, tid, rowBase, colBase, K, N, A, B);
    load_stage(sbase + STG_B, 1, tid, rowBase, colBase, K, N, A, B);

    const int aRow = warpM * 64 + (lane & 15);
    const uint32_t aColOff = (uint32_t)((lane >> 4) * 16);
    const int bRowOff = ((lane >> 3) & 1) * 8 + (lane & 7);
    const uint32_t bColB = (uint32_t)(warpN * 64 + ((lane >> 4) & 1) * 16);

    for (int c = 0; c < nc; c++) {
        if (c + 1 < nc) { CP_WAIT1(); } else { CP_WAIT0(); }
        __syncthreads();
        uint32_t sb = sbase + (uint32_t)(c & 1) * STG_B;

#pragma unroll
        for (int kk = 0; kk < 2; kk++) {
            uint32_t ah[4][4];
#pragma unroll
            for (int mt = 0; mt < 4; mt++)
                ldsm_x4(ah[mt], sb + (uint32_t)((aRow + mt * 16) * 80)
                              + (uint32_t)(kk * 32) + aColOff);
#pragma unroll
            for (int ng = 0; ng < 2; ng++) {
                uint32_t r[4];
                uint32_t baddr = sb + BT_OFF
                    + (uint32_t)((kk * 16 + bRowOff) * 272)
                    + bColB + (uint32_t)(ng * 32);
                ldsm_x4_t(r, baddr);
#pragma unroll
                for (int mt = 0; mt < 4; mt++) {
                    mma_f16(acc[mt][2 * ng],     ah[mt], r);
                    mma_f16(acc[mt][2 * ng + 1], ah[mt], r + 2);
                }
            }
        }
        __syncthreads();
        if (c + 2 < nc)
            load_stage(sbase + (uint32_t)(c & 1) * STG_B, c + 2, tid,
                       rowBase, colBase, K, N, A, B);
    }

#pragma unroll
    for (int mt = 0; mt < 4; mt++) {
        int row0 = rowBase + warpM * 64 + mt * 16 + (lane >> 2);
#pragma unroll
        for (int nt = 0; nt < 4; nt++) {
            int col = colBase + warpN * 32 + nt * 8 + (lane & 3) * 2;
            float b0 = bias[col], b1 = bias[col + 1];
#pragma unroll
            for (int half = 0; half < 2; half++) {
                int row = row0 + half * 8;
                float v0 = acc[mt][nt][half * 2 + 0] + b0;
                float v1 = acc[mt][nt][half * 2 + 1] + b1;
                if (MODE == 1) {
                    size_t pr = (size_t)(row & (NT - 1)) * N + col;
                    v0 += extra[pr]; v1 += extra[pr + 1];
                }
                if (MODE == 3) {
                    __half2 e = *(const __half2*)(extraH + (size_t)row * N + col);
                    v0 += __half2float(e.x); v1 += __half2float(e.y);
                }
                if (MODE == 2) { v0 = gelu_exact(v0); v1 = gelu_exact(v1); }
                *(__half2*)(Ch + (size_t)row * N + col) =
                    __half2(__float2half(v0), __float2half(v1));
            }
        }
    }
}

// ---------------- vectorized fp32 -> fp16 convert ----------------
__global__ __launch_bounds__(256)
void cvt4(const float* __restrict__ x, __half* __restrict__ o, size_t n) {
    size_t i = ((size_t)blockIdx.x * 256 + threadIdx.x) * 4;
    if (i < n) {
        float4 v = *(const float4*)(x + i);
        __half2 h0 = __floats2half2_rn(v.x, v.y);
        __half2 h1 = __floats2half2_rn(v.z, v.w);
        uint2 u; u.x = *(uint32_t*)&h0; u.y = *(uint32_t*)&h1;
        *(uint2*)(o + i) = u;
    }
}

// ---------------- LayerNorm over fp16 input: OUT=0 fp32, OUT=1 fp16 --------
template<int OUT>
__global__ __launch_bounds__(256)
void ln_kernel(const __half* __restrict__ x, const float* __restrict__ g,
               const float* __restrict__ b, float* __restrict__ yf,
               __half* __restrict__ yh, size_t rowStride)
{
    __shared__ float red[18];
    const int row = blockIdx.x, tid = threadIdx.x;
    const __half* xr = x + (size_t)row * rowStride;
    uint2 raw = ((const uint2*)xr)[tid];
    float2 p0 = __half22float2(*(__half2*)&raw.x);
    float2 p1 = __half22float2(*(__half2*)&raw.y);
    float v0 = p0.x, v1 = p0.y, v2 = p1.x, v3 = p1.y;
    float s  = v0 + v1 + v2 + v3;
    float sq = v0*v0 + v1*v1 + v2*v2 + v3*v3;
#pragma unroll
    for (int o = 16; o > 0; o >>= 1) {
        s  += __shfl_xor_sync(0xffffffffu, s,  o);
        sq += __shfl_xor_sync(0xffffffffu, sq, o);
    }
    if ((tid & 31) == 0) { red[tid >> 5] = s; red[8 + (tid >> 5)] = sq; }
    __syncthreads();
    if (tid < 32) {
        float ws = (tid < 8) ? red[tid]     : 0.f;
        float wq = (tid < 8) ? red[8 + tid] : 0.f;
#pragma unroll
        for (int o = 4; o > 0; o >>= 1) {
            ws += __shfl_xor_sync(0xffffffffu, ws, o);
            wq += __shfl_xor_sync(0xffffffffu, wq, o);
        }
        if (tid == 0) { red[16] = ws; red[17] = wq; }
    }
    __syncthreads();
    float mean = red[16] * (1.f / ND);
    float var  = red[17] * (1.f / ND) - mean * mean;
    float rstd = rsqrtf(var + 1e-5f);
    float4 gg = ((const float4*)g)[tid];
    float4 bb = ((const float4*)b)[tid];
    float o0 = (v0 - mean) * rstd * gg.x + bb.x;
    float o1 = (v1 - mean) * rstd * gg.y + bb.y;
    float o2 = (v2 - mean) * rstd * gg.z + bb.z;
    float o3 = (v3 - mean) * rstd * gg.w + bb.w;
    if (OUT == 0) {
        float4 o4 = {o0, o1, o2, o3};
        ((float4*)(yf + (size_t)row * ND))[tid] = o4;
    } else {
        size_t base = (size_t)row * ND + tid * 4;
        *(__half2*)(yh + base)     = __half2(__float2half(o0), __float2half(o1));
        *(__half2*)(yh + base + 2) = __half2(__float2half(o2), __float2half(o3));
    }
}

// ---------------------------------------------------------------------------
// Tensor-core flash attention, causal, HD=64.
// ---------------------------------------------------------------------------
#define ASTB 144

__global__ __launch_bounds__(128)
void attn_mma(const __half* __restrict__ qkv, __half* __restrict__ oh)
{
    __shared__ __align__(16) unsigned char sQ[64 * ASTB];
    __shared__ __align__(16) unsigned char sK[64 * ASTB];
    __shared__ __align__(16) unsigned char sV[64 * ASTB];
    const int qt = blockIdx.x, h = blockIdx.y, b = blockIdx.z;
    const int tid = threadIdx.x;
    const int lane = tid & 31, w = tid >> 5;
    uint32_t q_s = smem_u32(sQ), k_s = smem_u32(sK), v_s = smem_u32(sV);

    {
        size_t tok0 = (size_t)(b * NT + qt * 64);
#pragma unroll
        for (int i = 0; i < 4; i++) {
            int idx = tid + i * 128;
            int m = idx >> 3, dq = (idx & 7) * 8;
            *(uint4*)(sQ + m * ASTB + dq * 2) =
                *(const uint4*)(qkv + (tok0 + m) * (3 * ND) + h * 64 + dq);
        }
    }
    __syncthreads();

    uint32_t aQ[4][4];
    {
        uint32_t base = q_s + (uint32_t)((w * 16 + (lane & 15)) * ASTB)
                      + (uint32_t)((lane >> 4) * 16);
#pragma unroll
        for (int kc = 0; kc < 4; kc++) ldsm_x4(aQ[kc], base + kc * 32);
    }

    float oAcc[8][4];
#pragma unroll
    for (int nt = 0; nt < 8; nt++)
#pragma unroll
        for (int e = 0; e < 4; e++) oAcc[nt][e] = 0.f;
    float mA = -1e30f, mB = -1e30f, lA = 0.f, lB = 0.f;
    const int rowA = qt * 64 + w * 16 + (lane >> 2);
    const int rowB = rowA + 8;
    const float scale = 0.125f;

    for (int kt = 0; kt <= qt; kt++) {
        __syncthreads();
        {
            size_t tok0 = (size_t)(b * NT + kt * 64);
#pragma unroll
            for (int i = 0; i < 4; i++) {
                int idx = tid + i * 128;
                int m = idx >> 3, dq = (idx & 7) * 8;
                const __half* src = qkv + (tok0 + m) * (3 * ND) + ND + h * 64 + dq;
                *(uint4*)(sK + m * ASTB + dq * 2) = *(const uint4*)src;
                *(uint4*)(sV + m * ASTB + dq * 2) = *(const uint4*)(src + ND);
            }
        }
        __syncthreads();

        float sAcc[8][4];
#pragma unroll
        for (int nt = 0; nt < 8; nt++)
#pragma unroll
            for (int e = 0; e < 4; e++) sAcc[nt][e] = 0.f;
#pragma unroll
        for (int ng = 0; ng < 4; ng++) {
            uint32_t rbase = k_s
                + (uint32_t)((ng * 16 + ((lane >> 4) & 1) * 8 + (lane & 7)) * ASTB)
                + (uint32_t)(((lane >> 3) & 1) * 16);
#pragma unroll
            for (int kc = 0; kc < 4; kc++) {
                uint32_t r[4];
                ldsm_x4(r, rbase + kc * 32);
                mma_f16(sAcc[2 * ng],     aQ[kc], r);
                mma_f16(sAcc[2 * ng + 1], aQ[kc], r + 2);
            }
        }

        int colBase = kt * 64 + (lane & 3) * 2;
        float tA = -1e30f, tB = -1e30f;
#pragma unroll
        for (int nt = 0; nt < 8; nt++) {
            int c0 = colBase + nt * 8, c1 = c0 + 1;
            sAcc[nt][0] = (c0 <= rowA) ? sAcc[nt][0] * scale : -1e30f;
            sAcc[nt][1] = (c1 <= rowA) ? sAcc[nt][1] * scale : -1e30f;
            sAcc[nt][2] = (c0 <= rowB) ? sAcc[nt][2] * scale : -1e30f;
            sAcc[nt][3] = (c1 <= rowB) ? sAcc[nt][3] * scale : -1e30f;
            tA = fmaxf(tA, fmaxf(sAcc[nt][0], sAcc[nt][1]));
            tB = fmaxf(tB, fmaxf(sAcc[nt][2], sAcc[nt][3]));
        }
        tA = fmaxf(tA, __shfl_xor_sync(0xffffffffu, tA, 1));
        tA = fmaxf(tA, __shfl_xor_sync(0xffffffffu, tA, 2));
        tB = fmaxf(tB, __shfl_xor_sync(0xffffffffu, tB, 1));
        tB = fmaxf(tB, __shfl_xor_sync(0xffffffffu, tB, 2));
        float mnA = fmaxf(mA, tA), mnB = fmaxf(mB, tB);
        float corrA = expf(mA - mnA), corrB = expf(mB - mnB);
        float lsA = 0.f, lsB = 0.f;
#pragma unroll
        for (int nt = 0; nt < 8; nt++) {
            sAcc[nt][0] = expf(sAcc[nt][0] - mnA);
            sAcc[nt][1] = expf(sAcc[nt][1] - mnA);
            sAcc[nt][2] = expf(sAcc[nt][2] - mnB);
            sAcc[nt][3] = expf(sAcc[nt][3] - mnB);
            lsA += sAcc[nt][0] + sAcc[nt][1];
            lsB += sAcc[nt][2] + sAcc[nt][3];
        }
        lsA += __shfl_xor_sync(0xffffffffu, lsA, 1);
        lsA += __shfl_xor_sync(0xffffffffu, lsA, 2);
        lsB += __shfl_xor_sync(0xffffffffu, lsB, 1);
        lsB += __shfl_xor_sync(0xffffffffu, lsB, 2);
        lA = lA * corrA + lsA; mA = mnA;
        lB = lB * corrB + lsB; mB = mnB;
#pragma unroll
        for (int nt = 0; nt < 8; nt++) {
            oAcc[nt][0] *= corrA; oAcc[nt][1] *= corrA;
            oAcc[nt][2] *= corrB; oAcc[nt][3] *= corrB;
        }

        uint32_t aP[4][4];
#pragma unroll
        for (int kc = 0; kc < 4; kc++) {
            __half2 h0 = __floats2half2_rn(sAcc[2*kc][0],   sAcc[2*kc][1]);
            __half2 h1 = __floats2half2_rn(sAcc[2*kc][2],   sAcc[2*kc][3]);
            __half2 h2 = __floats2half2_rn(sAcc[2*kc+1][0], sAcc[2*kc+1][1]);
            __half2 h3 = __floats2half2_rn(sAcc[2*kc+1][2], sAcc[2*kc+1][3]);
            aP[kc][0] = *(uint32_t*)&h0; aP[kc][1] = *(uint32_t*)&h1;
            aP[kc][2] = *(uint32_t*)&h2; aP[kc][3] = *(uint32_t*)&h3;
        }

#pragma unroll
        for (int dg = 0; dg < 4; dg++) {
#pragma unroll
            for (int kc = 0; kc < 4; kc++) {
                uint32_t r[4];
                uint32_t addr = v_s
                    + (uint32_t)((kc * 16 + ((lane >> 3) & 1) * 8 + (lane & 7)) * ASTB)
                    + (uint32_t)(dg * 32) + (uint32_t)(((lane >> 4) & 1) * 16);
                ldsm_x4_t(r, addr);
                mma_f16(oAcc[2 * dg],     aP[kc], r);
                mma_f16(oAcc[2 * dg + 1], aP[kc], r + 2);
            }
        }
    }

    float invA = 1.f / lA, invB = 1.f / lB;
    size_t tokA = (size_t)(b * NT) + rowA;
    size_t tokB = (size_t)(b * NT) + rowB;
    int col0 = h * 64 + (lane & 3) * 2;
#pragma unroll
    for (int nt = 0; nt < 8; nt++) {
        *(__half2*)(oh + tokA * ND + col0 + nt * 8) =
            __half2(__float2half(oAcc[nt][0] * invA), __float2half(oAcc[nt][1] * invA));
        *(__half2*)(oh + tokB * ND + col0 + nt * 8) =
            __half2(__float2half(oAcc[nt][2] * invB), __float2half(oAcc[nt][3] * invB));
    }
}

// ---------------- head + RVQ ----------------
__global__ __launch_bounds__(256)
void small_gemm(const float* __restrict__ A, const float* __restrict__ W,
                const float* __restrict__ bias, float* __restrict__ out,
                int K, int N, int doGelu)
{
    __shared__ float sA[ND];
    const int row = blockIdx.x, tid = threadIdx.x;
    for (int i = tid; i < K; i += 256) sA[i] = A[(size_t)row * K + i];
    __syncthreads();
    for (int col = tid; col < N; col += 256) {
        float acc = 0.f;
        for (int k = 0; k < K; k++) acc += sA[k] * W[(size_t)k * N + col];
        acc += bias[col];
        if (doGelu) acc = gelu_exact(acc);
        out[(size_t)row * N + col] = acc;
    }
}

__global__ __launch_bounds__(256)
void rvq_kernel(const float* __restrict__ z, const float* __restrict__ codebooks,
                const float* __restrict__ layer_scales, float* __restrict__ out)
{
    __shared__ float res[NO];
    __shared__ float bestd[256];
    __shared__ int   besti[256];
    const int row = blockIdx.x, tid = threadIdx.x;
    res[tid] = z[(size_t)row * NO + tid];
    float outv = 0.f;
    for (int q = 0; q < NQ; q++) {
        __syncthreads();
        const float* cb = codebooks + (size_t)q * NK * NO;
        float bd = 1e30f; int bi = 0;
        for (int c = tid; c < NK; c += 256) {
            const float* e = cb + (size_t)c * NO;
            float dot = 0.f, nrm = 0.f;
            for (int d = 0; d < NO; d += 4) {
                float4 e4 = *(const float4*)(e + d);
                dot += res[d]*e4.x + res[d+1]*e4.y + res[d+2]*e4.z + res[d+3]*e4.w;
                nrm += e4.x*e4.x + e4.y*e4.y + e4.z*e4.z + e4.w*e4.w;
            }
            float dist = nrm - 2.f * dot;
            if (dist < bd) { bd = dist; bi = c; }
        }
        bestd[tid] = bd; besti[tid] = bi;
        __syncthreads();
        for (int sft = 128; sft > 0; sft >>= 1) {
            if (tid < sft) {
                float od = bestd[tid + sft]; int oi = besti[tid + sft];
                if (od < bestd[tid] || (od == bestd[tid] && oi < besti[tid])) {
                    bestd[tid] = od; besti[tid] = oi;
                }
            }
            __syncthreads();
        }
        int best = besti[0];
        float sig = 1.f / (1.f + expf(-layer_scales[q]));
        float ev = cb[(size_t)best * NO + tid];
        outv += sig * ev;
        res[tid] = res[tid] - ev;
    }
    out[(size_t)row * NO + tid] = outv;
}

// ---------------------------------------------------------------------------
extern "C" void kernel_launch(void* const* d_in, const int* in_sizes, int n_in,
                              void* d_out, int out_size)
{
    const float* x      = (const float*)d_in[0];
    const float* w_in   = (const float*)d_in[1];
    const float* b_in   = (const float*)d_in[2];
    const float* pos    = (const float*)d_in[3];
    const float* ln1_g  = (const float*)d_in[4];
    const float* ln1_b  = (const float*)d_in[5];
    const float* qkv_w  = (const float*)d_in[6];
    const float* qkv_b  = (const float*)d_in[7];
    const float* proj_w = (const float*)d_in[8];
    const float* proj_b = (const float*)d_in[9];
    const float* ln2_g  = (const float*)d_in[10];
    const float* ln2_b  = (const float*)d_in[11];
    const float* ff1_w  = (const float*)d_in[12];
    const float* ff1_b  = (const float*)d_in[13];
    const float* ff2_w  = (const float*)d_in[14];
    const float* ff2_b  = (const float*)d_in[15];
    const float* lnf_g  = (const float*)d_in[16];
    const float* lnf_b  = (const float*)d_in[17];
    const float* out1_w = (const float*)d_in[18];
    const float* out1_b = (const float*)d_in[19];
    const float* out2_w = (const float*)d_in[20];
    const float* out2_b = (const float*)d_in[21];
    const float* codebooks    = (const float*)d_in[22];
    const float* layer_scales = (const float*)d_in[23];

    float *last, *z1, *z;
    __half *h, *wf, *af, *ff, *xf, *qkvh;
    cudaGetSymbolAddress((void**)&last, g_last);
    cudaGetSymbolAddress((void**)&z1,   g_z1);
    cudaGetSymbolAddress((void**)&z,    g_z);
    cudaGetSymbolAddress((void**)&h,    g_h);
    cudaGetSymbolAddress((void**)&wf,   g_wf);
    cudaGetSymbolAddress((void**)&af,   g_af);
    cudaGetSymbolAddress((void**)&ff,   g_ff);
    cudaGetSymbolAddress((void**)&xf,   g_xf);
    cudaGetSymbolAddress((void**)&qkvh, g_qkvh);

    cudaFuncSetAttribute(gemm_mma<1>, cudaFuncAttributeMaxDynamicSharedMemorySize, GSMEM);
    cudaFuncSetAttribute(gemm_mma<2>, cudaFuncAttributeMaxDynamicSharedMemorySize, GSMEM);
    cudaFuncSetAttribute(gemm_mma<3>, cudaFuncAttributeMaxDynamicSharedMemorySize, GSMEM);
    cudaFuncSetAttribute(gemm_mma<4>, cudaFuncAttributeMaxDynamicSharedMemorySize, GSMEM);

    const dim3 thr(256);
    auto cblk = [](size_t n) { return (unsigned)((n / 4 + 255) / 256); };

    // ---- conversions ----
    cvt4<<<cblk((size_t)NTOK * NC), thr>>>(x, xf, (size_t)NTOK * NC);
    cvt4<<<cblk((size_t)NC * ND), thr>>>(w_in, wf + OFF_WIN, (size_t)NC * ND);
    cvt4<<<cblk((size_t)6 * QKV_SZ), thr>>>(qkv_w,  wf + OFF_QKV,  (size_t)6 * QKV_SZ);
    cvt4<<<cblk((size_t)6 * PROJ_SZ), thr>>>(proj_w, wf + OFF_PROJ, (size_t)6 * PROJ_SZ);
    cvt4<<<cblk((size_t)6 * FF1_SZ), thr>>>(ff1_w,  wf + OFF_FF1,  (size_t)6 * FF1_SZ);
    cvt4<<<cblk((size_t)6 * FF2_SZ), thr>>>(ff2_w,  wf + OFF_FF2,  (size_t)6 * FF2_SZ);

    // ---- h = x @ w_in + b_in + pos (fp16 out) ----
    gemm_mma<1><<<dim3(ND/128, NTOK/128), thr, GSMEM>>>(
        xf, wf + OFF_WIN, b_in, pos, nullptr, h, NTOK, ND, NC);

    for (int l = 0; l < NL; l++) {
        ln_kernel<1><<<NTOK, thr>>>(h, ln1_g + (size_t)l*ND, ln1_b + (size_t)l*ND,
                                    nullptr, af, ND);
        gemm_mma<4><<<dim3(3*ND/128, NTOK/128), thr, GSMEM>>>(
            af, wf + OFF_QKV + (size_t)l*QKV_SZ,
            qkv_b + (size_t)l*3*ND, nullptr, nullptr, qkvh, NTOK, 3*ND, ND);
        attn_mma<<<dim3(NT/64, NH, NB), 128>>>(qkvh, af);
        gemm_mma<3><<<dim3(ND/128, NTOK/128), thr, GSMEM>>>(
            af, wf + OFF_PROJ + (size_t)l*PROJ_SZ,
            proj_b + (size_t)l*ND, nullptr, h, h, NTOK, ND, ND);
        ln_kernel<1><<<NTOK, thr>>>(h, ln2_g + (size_t)l*ND, ln2_b + (size_t)l*ND,
                                    nullptr, af, ND);
        gemm_mma<2><<<dim3(NFF/128, NTOK/128), thr, GSMEM>>>(
            af, wf + OFF_FF1 + (size_t)l*FF1_SZ,
            ff1_b + (size_t)l*NFF, nullptr, nullptr, ff, NTOK, NFF, ND);
        gemm_mma<3><<<dim3(ND/128, NTOK/128), thr, GSMEM>>>(
            ff, wf + OFF_FF2 + (size_t)l*FF2_SZ,
            ff2_b + (size_t)l*ND, nullptr, h, h, NTOK, ND, NFF);
    }

    // ---- head ----
    ln_kernel<0><<<NB, thr>>>(h + (size_t)(NT - 1) * ND, lnf_g, lnf_b,
                              last, nullptr, (size_t)NT * ND);
    small_gemm<<<NB, thr>>>(last, out1_w, out1_b, z1, ND, ND, 1);
    small_gemm<<<NB, thr>>>(z1, out2_w, out2_b, z, ND, NO, 0);
    rvq_kernel<<<NB, thr>>>(z, codebooks, layer_scales, (float*)d_out);
}

// round 17
// speedup vs baseline: 1.6601x; 1.1099x over previous
#include <cuda_runtime.h>
#include <cuda_fp16.h>
#include <math.h>
#include <stdint.h>

#define NB 32
#define NT 512
#define NC 256
#define ND 1024
#define NH 16
#define NL 6
#define NFF 4096
#define NO 256
#define NQ 8
#define NK 1024
#define NTOK (NB*NT)

#define QKV_SZ  (ND*3*ND)
#define PROJ_SZ (ND*ND)
#define FF1_SZ  (ND*NFF)
#define FF2_SZ  (NFF*ND)
#define OFF_WIN 0
#define OFF_QKV (NC*ND)
#define OFF_PROJ (OFF_QKV + 6*QKV_SZ)
#define OFF_FF1  (OFF_PROJ + 6*PROJ_SZ)
#define OFF_FF2  (OFF_FF1 + 6*FF1_SZ)
#define W_TOTAL  (OFF_FF2 + 6*FF2_SZ)

__device__ float g_last[NB * ND];
__device__ float g_z1  [NB * ND];
__device__ float g_z   [NB * NO];

__device__ __align__(16) __half g_h   [(size_t)NTOK * ND];   // fp16 residual
__device__ __align__(16) __half g_wf  [W_TOTAL];             // weights fp16 [K,N]
__device__ __align__(16) __half g_af  [(size_t)NTOK * ND];
__device__ __align__(16) __half g_ff  [(size_t)NTOK * NFF];
__device__ __align__(16) __half g_xf  [(size_t)NTOK * NC];
__device__ __align__(16) __half g_qkvh[(size_t)NTOK * 3 * ND];
// compact last-token buffers for layer-5 truncation (rows 32..127 zero)
__device__ __align__(16) __half g_hc [128 * ND];
__device__ __align__(16) __half g_ac [128 * ND];
__device__ __align__(16) __half g_afc[128 * ND];
__device__ __align__(16) __half g_ffc[128 * NFF];

__device__ __forceinline__ float gelu_exact(float v) {
    return 0.5f * v * (1.0f + erff(v * 0.70710678118654752f));
}
__device__ __forceinline__ uint32_t smem_u32(const void* p) {
    uint32_t a;
    asm("{ .reg .u64 t; cvta.to.shared.u64 t, %1; cvt.u32.u64 %0, t; }"
        : "=r"(a) : "l"(p));
    return a;
}
__device__ __forceinline__ void cp16(uint32_t dst, const void* src) {
    asm volatile("cp.async.cg.shared.global [%0], [%1], 16;"
                 :: "r"(dst), "l"(src) : "memory");
}
#define CP_COMMIT() asm volatile("cp.async.commit_group;" ::: "memory")
#define CP_WAIT1()  asm volatile("cp.async.wait_group 1;" ::: "memory")
#define CP_WAIT0()  asm volatile("cp.async.wait_group 0;" ::: "memory")

__device__ __forceinline__ void ldsm_x4(uint32_t* r, uint32_t addr) {
    asm volatile("ldmatrix.sync.aligned.m8n8.x4.shared.b16 {%0,%1,%2,%3}, [%4];"
                 : "=r"(r[0]), "=r"(r[1]), "=r"(r[2]), "=r"(r[3]) : "r"(addr));
}
__device__ __forceinline__ void ldsm_x4_t(uint32_t* r, uint32_t addr) {
    asm volatile("ldmatrix.sync.aligned.m8n8.x4.trans.shared.b16 {%0,%1,%2,%3}, [%4];"
                 : "=r"(r[0]), "=r"(r[1]), "=r"(r[2]), "=r"(r[3]) : "r"(addr));
}
__device__ __forceinline__ void mma_f16(float* d, const uint32_t* a, const uint32_t* b) {
    asm volatile("mma.sync.aligned.m16n8k16.row.col.f32.f16.f16.f32 "
                 "{%0,%1,%2,%3}, {%4,%5,%6,%7}, {%8,%9}, {%0,%1,%2,%3};"
                 : "+f"(d[0]), "+f"(d[1]), "+f"(d[2]), "+f"(d[3])
                 : "r"(a[0]), "r"(a[1]), "r"(a[2]), "r"(a[3]),
                   "r"(b[0]), "r"(b[1]));
}

// ---------------------------------------------------------------------------
// fp16 GEMM (R14 config — at the sm_103 legacy-mma issue ceiling).
// Block 128x128, BK=32, 256 thr (8 warps 2Mx4N), 2-stage cp.async, 2 CTAs/SM.
// MODE 1: +bias +pos(fp32) -> fp16   MODE 2: gelu(+bias) -> fp16
// MODE 3: +bias +extraH(fp16) -> fp16   MODE 4: +bias -> fp16
// ---------------------------------------------------------------------------
#define AT_B   10240
#define BT_OFF 10240
#define BT_B   8704
#define STG_B  (AT_B + BT_B)
#define GSMEM  (2*STG_B)

__device__ __forceinline__ void load_stage(
    uint32_t sb, int c, int tid, int rowBase, int colBase, int K, int N,
    const __half* __restrict__ A, const __half* __restrict__ B)
{
    size_t koff = (size_t)c * 32;
#pragma unroll
    for (int i = 0; i < 2; i++) {
        int lin = tid + (i << 8);
        int r = lin >> 2, q = lin & 3;
        cp16(sb + (uint32_t)(r * 80 + q * 16),
             A + (size_t)(rowBase + r) * K + koff + q * 8);
    }
#pragma unroll
    for (int i = 0; i < 2; i++) {
        int lin = tid + (i << 8);
        int r = lin >> 4, q = lin & 15;
        cp16(sb + BT_OFF + (uint32_t)(r * 272 + q * 16),
             B + (koff + r) * (size_t)N + colBase + q * 8);
    }
    CP_COMMIT();
}

template<int MODE>
__global__ __launch_bounds__(256, 2)
void gemm_mma(const __half* __restrict__ A, const __half* __restrict__ B,
              const float* __restrict__ bias, const float* __restrict__ extra,
              const __half* __restrict__ extraH, __half* __restrict__ Ch,
              int M, int N, int K)
{
    extern __shared__ __align__(1024) unsigned char dynsmem[];
    uint32_t sbase = smem_u32(dynsmem);
    const int tid = threadIdx.x;
    const int lane = tid & 31;
    const int warp = tid >> 5;
    const int warpM = warp & 1;
    const int warpN = warp >> 1;
    const int rowBase = blockIdx.y * 128;
    const int colBase = blockIdx.x * 128;
    const int nc = K >> 5;

    float acc[4][4][4];
#pragma unroll
    for (int mt = 0; mt < 4; mt++)
#pragma unroll
        for (int nt = 0; nt < 4; nt++)
#pragma unroll
            for (int e = 0; e < 4; e++) acc[mt][nt][e] = 0.f;

    load_stage(sbase,         0, tid, rowBase, colBase, K, N, A, B);
    load_stage(sbase + STG_B, 1, tid, rowBase, colBase, K, N, A, B);

    const int aRow = warpM * 64 + (lane & 15);
    const uint32_t aColOff = (uint32_t)((lane >> 4) * 16);
    const int bRowOff = ((lane >> 3) & 1) * 8 + (lane & 7);
    const uint32_t bColB = (uint32_t)(warpN * 64 + ((lane >> 4) & 1) * 16);

    for (int c = 0; c < nc; c++) {
        if (c + 1 < nc) { CP_WAIT1(); } else { CP_WAIT0(); }
        __syncthreads();
        uint32_t sb = sbase + (uint32_t)(c & 1) * STG_B;

#pragma unroll
        for (int kk = 0; kk < 2; kk++) {
            uint32_t ah[4][4];
#pragma unroll
            for (int mt = 0; mt < 4; mt++)
                ldsm_x4(ah[mt], sb + (uint32_t)((aRow + mt * 16) * 80)
                              + (uint32_t)(kk * 32) + aColOff);
#pragma unroll
            for (int ng = 0; ng < 2; ng++) {
                uint32_t r[4];
                uint32_t baddr = sb + BT_OFF
                    + (uint32_t)((kk * 16 + bRowOff) * 272)
                    + bColB + (uint32_t)(ng * 32);
                ldsm_x4_t(r, baddr);
#pragma unroll
                for (int mt = 0; mt < 4; mt++) {
                    mma_f16(acc[mt][2 * ng],     ah[mt], r);
                    mma_f16(acc[mt][2 * ng + 1], ah[mt], r + 2);
                }
            }
        }
        __syncthreads();
        if (c + 2 < nc)
            load_stage(sbase + (uint32_t)(c & 1) * STG_B, c + 2, tid,
                       rowBase, colBase, K, N, A, B);
    }

#pragma unroll
    for (int mt = 0; mt < 4; mt++) {
        int row0 = rowBase + warpM * 64 + mt * 16 + (lane >> 2);
#pragma unroll
        for (int nt = 0; nt < 4; nt++) {
            int col = colBase + warpN * 32 + nt * 8 + (lane & 3) * 2;
            float b0 = bias[col], b1 = bias[col + 1];
#pragma unroll
            for (int half = 0; half < 2; half++) {
                int row = row0 + half * 8;
                float v0 = acc[mt][nt][half * 2 + 0] + b0;
                float v1 = acc[mt][nt][half * 2 + 1] + b1;
                if (MODE == 1) {
                    size_t pr = (size_t)(row & (NT - 1)) * N + col;
                    v0 += extra[pr]; v1 += extra[pr + 1];
                }
                if (MODE == 3) {
                    __half2 e = *(const __half2*)(extraH + (size_t)row * N + col);
                    v0 += __half2float(e.x); v1 += __half2float(e.y);
                }
                if (MODE == 2) { v0 = gelu_exact(v0); v1 = gelu_exact(v1); }
                *(__half2*)(Ch + (size_t)row * N + col) =
                    __half2(__float2half(v0), __float2half(v1));
            }
        }
    }
}

// ---------------- vectorized fp32 -> fp16 convert ----------------
__global__ __launch_bounds__(256)
void cvt4(const float* __restrict__ x, __half* __restrict__ o, size_t n) {
    size_t i = ((size_t)blockIdx.x * 256 + threadIdx.x) * 4;
    if (i < n) {
        float4 v = *(const float4*)(x + i);
        __half2 h0 = __floats2half2_rn(v.x, v.y);
        __half2 h1 = __floats2half2_rn(v.z, v.w);
        uint2 u; u.x = *(uint32_t*)&h0; u.y = *(uint32_t*)&h1;
        *(uint2*)(o + i) = u;
    }
}

// ---------------- gather last-token rows into compact buffers --------------
__global__ __launch_bounds__(256)
void gather32(const __half* __restrict__ h, const __half* __restrict__ af,
              __half* __restrict__ hc, __half* __restrict__ ac)
{
    const int r = blockIdx.x, tid = threadIdx.x;
    if (r < NB) {
        size_t src = ((size_t)r * NT + NT - 1) * ND;
        ((uint2*)(hc + (size_t)r * ND))[tid] = ((const uint2*)(h + src))[tid];
        ((uint2*)(ac + (size_t)r * ND))[tid] = ((const uint2*)(af + src))[tid];
    } else {
        uint2 z; z.x = 0u; z.y = 0u;
        ((uint2*)(hc + (size_t)r * ND))[tid] = z;
        ((uint2*)(ac + (size_t)r * ND))[tid] = z;
    }
}

// ---------------- LayerNorm over fp16 input: OUT=0 fp32, OUT=1 fp16 --------
template<int OUT>
__global__ __launch_bounds__(256)
void ln_kernel(const __half* __restrict__ x, const float* __restrict__ g,
               const float* __restrict__ b, float* __restrict__ yf,
               __half* __restrict__ yh, size_t rowStride)
{
    __shared__ float red[18];
    const int row = blockIdx.x, tid = threadIdx.x;
    const __half* xr = x + (size_t)row * rowStride;
    uint2 raw = ((const uint2*)xr)[tid];
    float2 p0 = __half22float2(*(__half2*)&raw.x);
    float2 p1 = __half22float2(*(__half2*)&raw.y);
    float v0 = p0.x, v1 = p0.y, v2 = p1.x, v3 = p1.y;
    float s  = v0 + v1 + v2 + v3;
    float sq = v0*v0 + v1*v1 + v2*v2 + v3*v3;
#pragma unroll
    for (int o = 16; o > 0; o >>= 1) {
        s  += __shfl_xor_sync(0xffffffffu, s,  o);
        sq += __shfl_xor_sync(0xffffffffu, sq, o);
    }
    if ((tid & 31) == 0) { red[tid >> 5] = s; red[8 + (tid >> 5)] = sq; }
    __syncthreads();
    if (tid < 32) {
        float ws = (tid < 8) ? red[tid]     : 0.f;
        float wq = (tid < 8) ? red[8 + tid] : 0.f;
#pragma unroll
        for (int o = 4; o > 0; o >>= 1) {
            ws += __shfl_xor_sync(0xffffffffu, ws, o);
            wq += __shfl_xor_sync(0xffffffffu, wq, o);
        }
        if (tid == 0) { red[16] = ws; red[17] = wq; }
    }
    __syncthreads();
    float mean = red[16] * (1.f / ND);
    float var  = red[17] * (1.f / ND) - mean * mean;
    float rstd = rsqrtf(var + 1e-5f);
    float4 gg = ((const float4*)g)[tid];
    float4 bb = ((const float4*)b)[tid];
    float o0 = (v0 - mean) * rstd * gg.x + bb.x;
    float o1 = (v1 - mean) * rstd * gg.y + bb.y;
    float o2 = (v2 - mean) * rstd * gg.z + bb.z;
    float o3 = (v3 - mean) * rstd * gg.w + bb.w;
    if (OUT == 0) {
        float4 o4 = {o0, o1, o2, o3};
        ((float4*)(yf + (size_t)row * ND))[tid] = o4;
    } else {
        size_t base = (size_t)row * ND + tid * 4;
        *(__half2*)(yh + base)     = __half2(__float2half(o0), __float2half(o1));
        *(__half2*)(yh + base + 2) = __half2(__float2half(o2), __float2half(o3));
    }
}

// ---------------------------------------------------------------------------
// Tensor-core flash attention, causal, HD=64. qt0 offsets the q-tile index.
// ---------------------------------------------------------------------------
#define ASTB 144

__global__ __launch_bounds__(128)
void attn_mma(const __half* __restrict__ qkv, __half* __restrict__ oh, int qt0)
{
    __shared__ __align__(16) unsigned char sQ[64 * ASTB];
    __shared__ __align__(16) unsigned char sK[64 * ASTB];
    __shared__ __align__(16) unsigned char sV[64 * ASTB];
    const int qt = blockIdx.x + qt0, h = blockIdx.y, b = blockIdx.z;
    const int tid = threadIdx.x;
    const int lane = tid & 31, w = tid >> 5;
    uint32_t q_s = smem_u32(sQ), k_s = smem_u32(sK), v_s = smem_u32(sV);

    {
        size_t tok0 = (size_t)(b * NT + qt * 64);
#pragma unroll
        for (int i = 0; i < 4; i++) {
            int idx = tid + i * 128;
            int m = idx >> 3, dq = (idx & 7) * 8;
            *(uint4*)(sQ + m * ASTB + dq * 2) =
                *(const uint4*)(qkv + (tok0 + m) * (3 * ND) + h * 64 + dq);
        }
    }
    __syncthreads();

    uint32_t aQ[4][4];
    {
        uint32_t base = q_s + (uint32_t)((w * 16 + (lane & 15)) * ASTB)
                      + (uint32_t)((lane >> 4) * 16);
#pragma unroll
        for (int kc = 0; kc < 4; kc++) ldsm_x4(aQ[kc], base + kc * 32);
    }

    float oAcc[8][4];
#pragma unroll
    for (int nt = 0; nt < 8; nt++)
#pragma unroll
        for (int e = 0; e < 4; e++) oAcc[nt][e] = 0.f;
    float mA = -1e30f, mB = -1e30f, lA = 0.f, lB = 0.f;
    const int rowA = qt * 64 + w * 16 + (lane >> 2);
    const int rowB = rowA + 8;
    const float scale = 0.125f;

    for (int kt = 0; kt <= qt; kt++) {
        __syncthreads();
        {
            size_t tok0 = (size_t)(b * NT + kt * 64);
#pragma unroll
            for (int i = 0; i < 4; i++) {
                int idx = tid + i * 128;
                int m = idx >> 3, dq = (idx & 7) * 8;
                const __half* src = qkv + (tok0 + m) * (3 * ND) + ND + h * 64 + dq;
                *(uint4*)(sK + m * ASTB + dq * 2) = *(const uint4*)src;
                *(uint4*)(sV + m * ASTB + dq * 2) = *(const uint4*)(src + ND);
            }
        }
        __syncthreads();

        float sAcc[8][4];
#pragma unroll
        for (int nt = 0; nt < 8; nt++)
#pragma unroll
            for (int e = 0; e < 4; e++) sAcc[nt][e] = 0.f;
#pragma unroll
        for (int ng = 0; ng < 4; ng++) {
            uint32_t rbase = k_s
                + (uint32_t)((ng * 16 + ((lane >> 4) & 1) * 8 + (lane & 7)) * ASTB)
                + (uint32_t)(((lane >> 3) & 1) * 16);
#pragma unroll
            for (int kc = 0; kc < 4; kc++) {
                uint32_t r[4];
                ldsm_x4(r, rbase + kc * 32);
                mma_f16(sAcc[2 * ng],     aQ[kc], r);
                mma_f16(sAcc[2 * ng + 1], aQ[kc], r + 2);
            }
        }

        int colBase = kt * 64 + (lane & 3) * 2;
        float tA = -1e30f, tB = -1e30f;
#pragma unroll
        for (int nt = 0; nt < 8; nt++) {
            int c0 = colBase + nt * 8, c1 = c0 + 1;
            sAcc[nt][0] = (c0 <= rowA) ? sAcc[nt][0] * scale : -1e30f;
            sAcc[nt][1] = (c1 <= rowA) ? sAcc[nt][1] * scale : -1e30f;
            sAcc[nt][2] = (c0 <= rowB) ? sAcc[nt][2] * scale : -1e30f;
            sAcc[nt][3] = (c1 <= rowB) ? sAcc[nt][3] * scale : -1e30f;
            tA = fmaxf(tA, fmaxf(sAcc[nt][0], sAcc[nt][1]));
            tB = fmaxf(tB, fmaxf(sAcc[nt][2], sAcc[nt][3]));
        }
        tA = fmaxf(tA, __shfl_xor_sync(0xffffffffu, tA, 1));
        tA = fmaxf(tA, __shfl_xor_sync(0xffffffffu, tA, 2));
        tB = fmaxf(tB, __shfl_xor_sync(0xffffffffu, tB, 1));
        tB = fmaxf(tB, __shfl_xor_sync(0xffffffffu, tB, 2));
        float mnA = fmaxf(mA, tA), mnB = fmaxf(mB, tB);
        float corrA = expf(mA - mnA), corrB = expf(mB - mnB);
        float lsA = 0.f, lsB = 0.f;
#pragma unroll
        for (int nt = 0; nt < 8; nt++) {
            sAcc[nt][0] = expf(sAcc[nt][0] - mnA);
            sAcc[nt][1] = expf(sAcc[nt][1] - mnA);
            sAcc[nt][2] = expf(sAcc[nt][2] - mnB);
            sAcc[nt][3] = expf(sAcc[nt][3] - mnB);
            lsA += sAcc[nt][0] + sAcc[nt][1];
            lsB += sAcc[nt][2] + sAcc[nt][3];
        }
        lsA += __shfl_xor_sync(0xffffffffu, lsA, 1);
        lsA += __shfl_xor_sync(0xffffffffu, lsA, 2);
        lsB += __shfl_xor_sync(0xffffffffu, lsB, 1);
        lsB += __shfl_xor_sync(0xffffffffu, lsB, 2);
        lA = lA * corrA + lsA; mA = mnA;
        lB = lB * corrB + lsB; mB = mnB;
#pragma unroll
        for (int nt = 0; nt < 8; nt++) {
            oAcc[nt][0] *= corrA; oAcc[nt][1] *= corrA;
            oAcc[nt][2] *= corrB; oAcc[nt][3] *= corrB;
        }

        uint32_t aP[4][4];
#pragma unroll
        for (int kc = 0; kc < 4; kc++) {
            __half2 h0 = __floats2half2_rn(sAcc[2*kc][0],   sAcc[2*kc][1]);
            __half2 h1 = __floats2half2_rn(sAcc[2*kc][2],   sAcc[2*kc][3]);
            __half2 h2 = __floats2half2_rn(sAcc[2*kc+1][0], sAcc[2*kc+1][1]);
            __half2 h3 = __floats2half2_rn(sAcc[2*kc+1][2], sAcc[2*kc+1][3]);
            aP[kc][0] = *(uint32_t*)&h0; aP[kc][1] = *(uint32_t*)&h1;
            aP[kc][2] = *(uint32_t*)&h2; aP[kc][3] = *(uint32_t*)&h3;
        }

#pragma unroll
        for (int dg = 0; dg < 4; dg++) {
#pragma unroll
            for (int kc = 0; kc < 4; kc++) {
                uint32_t r[4];
                uint32_t addr = v_s
                    + (uint32_t)((kc * 16 + ((lane >> 3) & 1) * 8 + (lane & 7)) * ASTB)
                    + (uint32_t)(dg * 32) + (uint32_t)(((lane >> 4) & 1) * 16);
                ldsm_x4_t(r, addr);
                mma_f16(oAcc[2 * dg],     aP[kc], r);
                mma_f16(oAcc[2 * dg + 1], aP[kc], r + 2);
            }
        }
    }

    float invA = 1.f / lA, invB = 1.f / lB;
    size_t tokA = (size_t)(b * NT) + rowA;
    size_t tokB = (size_t)(b * NT) + rowB;
    int col0 = h * 64 + (lane & 3) * 2;
#pragma unroll
    for (int nt = 0; nt < 8; nt++) {
        *(__half2*)(oh + tokA * ND + col0 + nt * 8) =
            __half2(__float2half(oAcc[nt][0] * invA), __float2half(oAcc[nt][1] * invA));
        *(__half2*)(oh + tokB * ND + col0 + nt * 8) =
            __half2(__float2half(oAcc[nt][2] * invB), __float2half(oAcc[nt][3] * invB));
    }
}

// ---------------- head + RVQ ----------------
__global__ __launch_bounds__(256)
void small_gemm(const float* __restrict__ A, const float* __restrict__ W,
                const float* __restrict__ bias, float* __restrict__ out,
                int K, int N, int doGelu)
{
    __shared__ float sA[ND];
    const int row = blockIdx.x, tid = threadIdx.x;
    for (int i = tid; i < K; i += 256) sA[i] = A[(size_t)row * K + i];
    __syncthreads();
    for (int col = tid; col < N; col += 256) {
        float acc = 0.f;
        for (int k = 0; k < K; k++) acc += sA[k] * W[(size_t)k * N + col];
        acc += bias[col];
        if (doGelu) acc = gelu_exact(acc);
        out[(size_t)row * N + col] = acc;
    }
}

__global__ __launch_bounds__(256)
void rvq_kernel(const float* __restrict__ z, const float* __restrict__ codebooks,
                const float* __restrict__ layer_scales, float* __restrict__ out)
{
    __shared__ float res[NO];
    __shared__ float bestd[256];
    __shared__ int   besti[256];
    const int row = blockIdx.x, tid = threadIdx.x;
    res[tid] = z[(size_t)row * NO + tid];
    float outv = 0.f;
    for (int q = 0; q < NQ; q++) {
        __syncthreads();
        const float* cb = codebooks + (size_t)q * NK * NO;
        float bd = 1e30f; int bi = 0;
        for (int c = tid; c < NK; c += 256) {
            const float* e = cb + (size_t)c * NO;
            float dot = 0.f, nrm = 0.f;
            for (int d = 0; d < NO; d += 4) {
                float4 e4 = *(const float4*)(e + d);
                dot += res[d]*e4.x + res[d+1]*e4.y + res[d+2]*e4.z + res[d+3]*e4.w;
                nrm += e4.x*e4.x + e4.y*e4.y + e4.z*e4.z + e4.w*e4.w;
            }
            float dist = nrm - 2.f * dot;
            if (dist < bd) { bd = dist; bi = c; }
        }
        bestd[tid] = bd; besti[tid] = bi;
        __syncthreads();
        for (int sft = 128; sft > 0; sft >>= 1) {
            if (tid < sft) {
                float od = bestd[tid + sft]; int oi = besti[tid + sft];
                if (od < bestd[tid] || (od == bestd[tid] && oi < besti[tid])) {
                    bestd[tid] = od; besti[tid] = oi;
                }
            }
            __syncthreads();
        }
        int best = besti[0];
        float sig = 1.f / (1.f + expf(-layer_scales[q]));
        float ev = cb[(size_t)best * NO + tid];
        outv += sig * ev;
        res[tid] = res[tid] - ev;
    }
    out[(size_t)row * NO + tid] = outv;
}

// ---------------------------------------------------------------------------
extern "C" void kernel_launch(void* const* d_in, const int* in_sizes, int n_in,
                              void* d_out, int out_size)
{
    const float* x      = (const float*)d_in[0];
    const float* w_in   = (const float*)d_in[1];
    const float* b_in   = (const float*)d_in[2];
    const float* pos    = (const float*)d_in[3];
    const float* ln1_g  = (const float*)d_in[4];
    const float* ln1_b  = (const float*)d_in[5];
    const float* qkv_w  = (const float*)d_in[6];
    const float* qkv_b  = (const float*)d_in[7];
    const float* proj_w = (const float*)d_in[8];
    const float* proj_b = (const float*)d_in[9];
    const float* ln2_g  = (const float*)d_in[10];
    const float* ln2_b  = (const float*)d_in[11];
    const float* ff1_w  = (const float*)d_in[12];
    const float* ff1_b  = (const float*)d_in[13];
    const float* ff2_w  = (const float*)d_in[14];
    const float* ff2_b  = (const float*)d_in[15];
    const float* lnf_g  = (const float*)d_in[16];
    const float* lnf_b  = (const float*)d_in[17];
    const float* out1_w = (const float*)d_in[18];
    const float* out1_b = (const float*)d_in[19];
    const float* out2_w = (const float*)d_in[20];
    const float* out2_b = (const float*)d_in[21];
    const float* codebooks    = (const float*)d_in[22];
    const float* layer_scales = (const float*)d_in[23];

    float *last, *z1, *z;
    __half *h, *wf, *af, *ff, *xf, *qkvh, *hc, *ac, *afc, *ffc;
    cudaGetSymbolAddress((void**)&last, g_last);
    cudaGetSymbolAddress((void**)&z1,   g_z1);
    cudaGetSymbolAddress((void**)&z,    g_z);
    cudaGetSymbolAddress((void**)&h,    g_h);
    cudaGetSymbolAddress((void**)&wf,   g_wf);
    cudaGetSymbolAddress((void**)&af,   g_af);
    cudaGetSymbolAddress((void**)&ff,   g_ff);
    cudaGetSymbolAddress((void**)&xf,   g_xf);
    cudaGetSymbolAddress((void**)&qkvh, g_qkvh);
    cudaGetSymbolAddress((void**)&hc,   g_hc);
    cudaGetSymbolAddress((void**)&ac,   g_ac);
    cudaGetSymbolAddress((void**)&afc,  g_afc);
    cudaGetSymbolAddress((void**)&ffc,  g_ffc);

    cudaFuncSetAttribute(gemm_mma<1>, cudaFuncAttributeMaxDynamicSharedMemorySize, GSMEM);
    cudaFuncSetAttribute(gemm_mma<2>, cudaFuncAttributeMaxDynamicSharedMemorySize, GSMEM);
    cudaFuncSetAttribute(gemm_mma<3>, cudaFuncAttributeMaxDynamicSharedMemorySize, GSMEM);
    cudaFuncSetAttribute(gemm_mma<4>, cudaFuncAttributeMaxDynamicSharedMemorySize, GSMEM);

    const dim3 thr(256);
    auto cblk = [](size_t n) { return (unsigned)((n / 4 + 255) / 256); };

    // ---- conversions ----
    cvt4<<<cblk((size_t)NTOK * NC), thr>>>(x, xf, (size_t)NTOK * NC);
    cvt4<<<cblk((size_t)NC * ND), thr>>>(w_in, wf + OFF_WIN, (size_t)NC * ND);
    cvt4<<<cblk((size_t)6 * QKV_SZ), thr>>>(qkv_w,  wf + OFF_QKV,  (size_t)6 * QKV_SZ);
    cvt4<<<cblk((size_t)6 * PROJ_SZ), thr>>>(proj_w, wf + OFF_PROJ, (size_t)6 * PROJ_SZ);
    cvt4<<<cblk((size_t)6 * FF1_SZ), thr>>>(ff1_w,  wf + OFF_FF1,  (size_t)6 * FF1_SZ);
    cvt4<<<cblk((size_t)6 * FF2_SZ), thr>>>(ff2_w,  wf + OFF_FF2,  (size_t)6 * FF2_SZ);

    // ---- h = x @ w_in + b_in + pos (fp16 out) ----
    gemm_mma<1><<<dim3(ND/128, NTOK/128), thr, GSMEM>>>(
        xf, wf + OFF_WIN, b_in, pos, nullptr, h, NTOK, ND, NC);

    // ---- layers 0..4: full-width ----
    for (int l = 0; l < NL - 1; l++) {
        ln_kernel<1><<<NTOK, thr>>>(h, ln1_g + (size_t)l*ND, ln1_b + (size_t)l*ND,
                                    nullptr, af, ND);
        gemm_mma<4><<<dim3(3*ND/128, NTOK/128), thr, GSMEM>>>(
            af, wf + OFF_QKV + (size_t)l*QKV_SZ,
            qkv_b + (size_t)l*3*ND, nullptr, nullptr, qkvh, NTOK, 3*ND, ND);
        attn_mma<<<dim3(NT/64, NH, NB), 128>>>(qkvh, af, 0);
        gemm_mma<3><<<dim3(ND/128, NTOK/128), thr, GSMEM>>>(
            af, wf + OFF_PROJ + (size_t)l*PROJ_SZ,
            proj_b + (size_t)l*ND, nullptr, h, h, NTOK, ND, ND);
        ln_kernel<1><<<NTOK, thr>>>(h, ln2_g + (size_t)l*ND, ln2_b + (size_t)l*ND,
                                    nullptr, af, ND);
        gemm_mma<2><<<dim3(NFF/128, NTOK/128), thr, GSMEM>>>(
            af, wf + OFF_FF1 + (size_t)l*FF1_SZ,
            ff1_b + (size_t)l*NFF, nullptr, nullptr, ff, NTOK, NFF, ND);
        gemm_mma<3><<<dim3(ND/128, NTOK/128), thr, GSMEM>>>(
            ff, wf + OFF_FF2 + (size_t)l*FF2_SZ,
            ff2_b + (size_t)l*ND, nullptr, h, h, NTOK, ND, NFF);
    }

    // ---- layer 5: only last token per batch matters after attention ----
    {
        const int l = NL - 1;
        ln_kernel<1><<<NTOK, thr>>>(h, ln1_g + (size_t)l*ND, ln1_b + (size_t)l*ND,
                                    nullptr, af, ND);
        gemm_mma<4><<<dim3(3*ND/128, NTOK/128), thr, GSMEM>>>(
            af, wf + OFF_QKV + (size_t)l*QKV_SZ,
            qkv_b + (size_t)l*3*ND, nullptr, nullptr, qkvh, NTOK, 3*ND, ND);
        // only the last q-tile's outputs are consumed
        attn_mma<<<dim3(1, NH, NB), 128>>>(qkvh, af, NT/64 - 1);
        // gather 32 last-token rows (h residual + attn out) into compact bufs
        gather32<<<128, thr>>>(h, af, hc, ac);
        // proj + residual on compact M=128
        gemm_mma<3><<<dim3(ND/128, 1), thr, GSMEM>>>(
            ac, wf + OFF_PROJ + (size_t)l*PROJ_SZ,
            proj_b + (size_t)l*ND, nullptr, hc, hc, 128, ND, ND);
        ln_kernel<1><<<NB, thr>>>(hc, ln2_g + (size_t)l*ND, ln2_b + (size_t)l*ND,
                                  nullptr, afc, ND);
        gemm_mma<2><<<dim3(NFF/128, 1), thr, GSMEM>>>(
            afc, wf + OFF_FF1 + (size_t)l*FF1_SZ,
            ff1_b + (size_t)l*NFF, nullptr, nullptr, ffc, 128, NFF, ND);
        gemm_mma<3><<<dim3(ND/128, 1), thr, GSMEM>>>(
            ffc, wf + OFF_FF2 + (size_t)l*FF2_SZ,
            ff2_b + (size_t)l*ND, nullptr, hc, hc, 128, ND, NFF);
    }

    // ---- head (compact rows are contiguous) ----
    ln_kernel<0><<<NB, thr>>>(hc, lnf_g, lnf_b, last, nullptr, ND);
    small_gemm<<<NB, thr>>>(last, out1_w, out1_b, z1, ND, ND, 1);
    small_gemm<<<NB, thr>>>(z1, out2_w, out2_b, z, ND, NO, 0);
    rvq_kernel<<<NB, thr>>>(z, codebooks, layer_scales, (float*)d_out);
}